// round 13
// baseline (speedup 1.0000x reference)
#include <cuda_runtime.h>
#include <cuda_bf16.h>
#include <cstdint>

// ---------------------------------------------------------------------------
// Problem constants
// ---------------------------------------------------------------------------
#define BATCH   8192
#define SEQ     8
#define HID     2048
#define NEXP    64
#define TOPK    8
#define ROWSTR  (SEQ * HID)

// GEMM config: BM=64, split-K=2 (256 CTAs, one wave at 2/SM).
// Warps 0-3: consumers (m32n32, LDSM A + direct-LDG B frags + MMA).
// Warps 4-7: producers (LDG A f32 -> split3 -> STS). B never touches smem.
// THREE-stage A pipeline to decouple producer/consumer jitter.
#define BM      64
#define KT      64                 // k-tile (f32 elements)
#define KSPL    2
#define KHALF   (HID / KSPL)       // 1024
#define NT      (KHALF / KT)       // 16 tiles per split

// smem: A only (bf16, 128B per row), TRIPLE buffered
#define A_PL    8192               // 64 rows x 128B
#define ABUF    (3 * A_PL)         // 24576 (3 split planes)
#define NSTG    3
#define SM_ALLOC (NSTG * ABUF + 1024)  // 74752 -> 2 CTAs/SM (149.5KB < 228KB)

// B fragment store: [plane(3)][n8 group(8)][k16 chunk(128)][lane(32)][2 u32]
#define NCH     (HID / 16)         // 128 k16 chunks

// Router config
#define RBLK    512
#define RTHR    512
#define RWARPS  (RTHR / 32)        // 16

// Scratch (no allocation allowed)
__device__ float    g_partial[KSPL][BATCH * NEXP];  // 4 MB
__device__ uint32_t g_bfrag[3 * 8 * NCH * 64];      // 768 KB, frag-ordered B
__device__ float    g_bimp[RBLK][NEXP];
__device__ int      g_bcnt[RBLK][NEXP];
__device__ unsigned g_done;

// ---------------------------------------------------------------------------
// helpers
// ---------------------------------------------------------------------------
__device__ __forceinline__ uint32_t smem_to_u32(const void* p) {
    uint32_t a;
    asm("{ .reg .u64 t; cvta.to.shared.u64 t, %1; cvt.u32.u64 %0, t; }"
        : "=r"(a) : "l"(p));
    return a;
}
__device__ __forceinline__ void ldsm4(uint32_t* r, uint32_t addr) {
    asm volatile("ldmatrix.sync.aligned.m8n8.x4.shared.b16 {%0,%1,%2,%3}, [%4];"
                 : "=r"(r[0]), "=r"(r[1]), "=r"(r[2]), "=r"(r[3]) : "r"(addr));
}
__device__ __forceinline__ void mma16816(float* d, const uint32_t* a,
                                         const uint32_t* b) {
    asm volatile(
        "mma.sync.aligned.m16n8k16.row.col.f32.bf16.bf16.f32 "
        "{%0,%1,%2,%3}, {%4,%5,%6,%7}, {%8,%9}, {%0,%1,%2,%3};"
        : "+f"(d[0]), "+f"(d[1]), "+f"(d[2]), "+f"(d[3])
        : "r"(a[0]), "r"(a[1]), "r"(a[2]), "r"(a[3]), "r"(b[0]), "r"(b[1]));
}
__device__ __forceinline__ uint32_t pack_bf16(float lo, float hi) {
    uint32_t r;
    asm("cvt.rn.bf16x2.f32 %0, %1, %2;" : "=r"(r) : "f"(hi), "f"(lo));
    return r;
}
// fp32 -> 3x bf16 split (byte-identical to the R8/R11-passing kernels)
__device__ __forceinline__ void split3(float x, float y,
                                       uint32_t& h, uint32_t& m, uint32_t& l) {
    h = pack_bf16(x, y);
    float hx = __uint_as_float(h << 16);
    float hy = __uint_as_float(h & 0xffff0000u);
    float rx = x - hx, ry = y - hy;
    m = pack_bf16(rx, ry);
    float mx = __uint_as_float(m << 16);
    float my = __uint_as_float(m & 0xffff0000u);
    l = pack_bf16(rx - mx, ry - my);
}
__device__ __forceinline__ void sts64(uint32_t addr, uint32_t a, uint32_t b) {
    asm volatile("st.shared.v2.b32 [%0], {%1, %2};"
                 :: "r"(addr), "r"(a), "r"(b) : "memory");
}
// named producer/consumer barriers (256 = all threads of the CTA)
#define BAR_SYNC(id)   asm volatile("bar.sync %0, 256;"   :: "r"(id) : "memory")
#define BAR_ARRIVE(id) asm volatile("bar.arrive %0, 256;" :: "r"(id) : "memory")

__device__ __forceinline__ int redux_max_s32(int v) {
    int r;
    asm("redux.sync.max.s32 %0, %1, 0xffffffff;" : "=r"(r) : "r"(v));
    return r;
}
__device__ __forceinline__ unsigned redux_max_u32(unsigned v) {
    unsigned r;
    asm("redux.sync.max.u32 %0, %1, 0xffffffff;" : "=r"(r) : "r"(v));
    return r;
}
__device__ __forceinline__ unsigned fenc(float f) {
    int b = __float_as_int(f);
    return (unsigned)(b ^ ((b >> 31) | 0x80000000));
}
__device__ __forceinline__ float fdec(unsigned u) {
    int b = (u & 0x80000000u) ? (int)(u ^ 0x80000000u) : (int)~u;
    return __int_as_float(b);
}

// ---------------------------------------------------------------------------
// Kernel 0: split gate_w into 3 bf16 planes in MMA FRAGMENT order (1 float2
// per thread) + reset ticket. Layout identical to R11.
// ---------------------------------------------------------------------------
__global__ void __launch_bounds__(256)
bsplit_kernel(const float* __restrict__ gw) {
    int id = blockIdx.x * 256 + threadIdx.x;   // 0..65535
    if (id == 0) g_done = 0u;

    int half = id & 1;
    int t    = (id >> 1) & 31;
    int c    = (id >> 6) & 127;
    int g    = id >> 13;                       // 0..7
    int n  = g * 8 + (t >> 2);
    int k0 = c * 16 + (t & 3) * 2 + half * 8;

    float2 v = *(const float2*)(gw + (size_t)n * HID + k0);
    uint32_t h, m, l;
    split3(v.x, v.y, h, m, l);

    int fi = (g * NCH + c) * 64 + t * 2 + half;
    const int PL = 8 * NCH * 64;               // plane stride in u32
    g_bfrag[fi]          = h;
    g_bfrag[PL + fi]     = m;
    g_bfrag[2 * PL + fi] = l;
}

// ---------------------------------------------------------------------------
// Kernel 1: HMMA logits GEMM, bf16 3-split (6 products), B via direct LDG,
// 3-stage A pipeline.
// ---------------------------------------------------------------------------
__global__ void __launch_bounds__(256, 2)
gemm_tc(const float* __restrict__ hs) {
    extern __shared__ char smem_raw[];
    const uint32_t sb = (smem_to_u32(smem_raw) + 1023u) & ~1023u;

    const int tid  = threadIdx.x;
    const int wid  = tid >> 5;
    const int lane = tid & 31;
    const int m0   = blockIdx.x * BM;
    const int sp   = blockIdx.y;
    const int k0   = sp * KHALF;

    if (wid < 4) {
        // =================== CONSUMER ===================
        const int wm = (wid & 1) * 32;
        const int wn = (wid >> 1) * 32;
        const int gbase = wn >> 3;             // first n8 group (0 or 4)

        uint32_t abase[2], amask[2];
#pragma unroll
        for (int mt = 0; mt < 2; mt++) {
            int row = wm + mt * 16 + (lane & 15);
            abase[mt] = (uint32_t)(row * 128 + (lane >> 4) * 16);
            amask[mt] = (uint32_t)((row & 7) << 4);
        }

        float acc[2][4][4];                    // [mt][n8 group j][4]
#pragma unroll
        for (int a = 0; a < 2; a++)
#pragma unroll
            for (int b = 0; b < 4; b++)
#pragma unroll
                for (int c = 0; c < 4; c++) acc[a][b][c] = 0.0f;

        const int pa[6] = {0, 0, 1, 0, 2, 1};  // hh, hm, mh, hl, lh, mm
        const int pb[6] = {0, 1, 0, 2, 0, 1};

        const int PL = 8 * NCH * 64;           // plane stride (u32)
        const int csp = sp * (KHALF / 16);     // first chunk of this split

        // B frag double buffer in registers (one kc ahead)
        uint2 bb0[3][4], bb1[3][4];
#define LOAD_B(dst, cc) do {                                                  \
    _Pragma("unroll")                                                         \
    for (int p = 0; p < 3; p++) {                                             \
        _Pragma("unroll")                                                     \
        for (int j = 0; j < 4; j++)                                           \
            (dst)[p][j] = __ldg((const uint2*)&g_bfrag[                       \
                p * PL + ((gbase + j) * NCH + (csp + (cc))) * 64] + lane);    \
    } } while (0)

        LOAD_B(bb0, 0);

        for (int t = 0; t < NT; t++) {
            const int buf = t % NSTG;
            const uint32_t aBase = sb + (uint32_t)buf * ABUF;

            BAR_SYNC(1 + buf);          // wait A tile full

#pragma unroll
            for (int kc = 0; kc < 4; kc++) {
                uint32_t af[3][2][4];
#pragma unroll
                for (int p = 0; p < 3; p++)
#pragma unroll
                    for (int mt = 0; mt < 2; mt++)
                        ldsm4(af[p][mt],
                              aBase + p * A_PL + ((abase[mt] + kc * 32) ^ amask[mt]));

                if (kc < 3) {
                    if (kc & 1) { LOAD_B(bb0, t * 4 + kc + 1); }
                    else        { LOAD_B(bb1, t * 4 + kc + 1); }
                } else if (t + 1 < NT) {
                    LOAD_B(bb0, t * 4 + 4);
                }

#pragma unroll
                for (int pr = 0; pr < 6; pr++) {
#pragma unroll
                    for (int mt = 0; mt < 2; mt++) {
#pragma unroll
                        for (int j = 0; j < 4; j++) {
                            const uint2* bf = (kc & 1) ? &bb1[pb[pr]][j]
                                                       : &bb0[pb[pr]][j];
                            mma16816(acc[mt][j], af[pa[pr]][mt],
                                     (const uint32_t*)bf);
                        }
                    }
                }
            }
            if (t + NSTG < NT) BAR_ARRIVE(4 + buf);   // A tile free
        }
#undef LOAD_B

        // epilogue: warp writes its 32x32 f32 tile to split partials
        const int gr = m0 + wm + (lane >> 2);
        const int gc = wn + (lane & 3) * 2;
#pragma unroll
        for (int mt = 0; mt < 2; mt++) {
#pragma unroll
            for (int j = 0; j < 4; j++) {
                int row = gr + mt * 16;
                int col = gc + j * 8;
                *(float2*)&g_partial[sp][(size_t)row * NEXP + col] =
                    make_float2(acc[mt][j][0], acc[mt][j][1]);
                *(float2*)&g_partial[sp][(size_t)(row + 8) * NEXP + col] =
                    make_float2(acc[mt][j][2], acc[mt][j][3]);
            }
        }
    } else {
        // =================== PRODUCER (A only) ===================
        const int wt = tid & 127;     // 0..127

        float4 ar[8], arn[8];
#define LOAD_A(t, dst) do {                                                   \
    int kk = k0 + (t) * KT;                                                   \
    _Pragma("unroll")                                                         \
    for (int i = 0; i < 8; i++) {                                             \
        int lin = wt + i * 128; int row = lin >> 4; int c4 = lin & 15;        \
        (dst)[i] = *(const float4*)(hs + (size_t)(m0 + row) * ROWSTR + kk + c4 * 4); \
    } } while (0)

        LOAD_A(0, ar);

        for (int t = 0; t < NT; t++) {
            const int buf = t % NSTG;
            const uint32_t aBase = sb + (uint32_t)buf * ABUF;

            if (t + 1 < NT) LOAD_A(t + 1, arn);
            if (t >= NSTG) BAR_SYNC(4 + buf);   // wait tile free

            // convert + swizzled store: A (3 planes, identical split3 values)
#pragma unroll
            for (int i = 0; i < 8; i++) {
                int lin = wt + i * 128; int row = lin >> 4; int c4 = lin & 15;
                uint32_t off = (uint32_t)(row * 128 + c4 * 8);
                uint32_t sw  = off ^ ((off >> 3) & 0x70u);
                uint32_t h0, mm0, l0, h1, mm1, l1;
                split3(ar[i].x, ar[i].y, h0, mm0, l0);
                split3(ar[i].z, ar[i].w, h1, mm1, l1);
                sts64(aBase + sw,            h0,  h1);
                sts64(aBase + A_PL + sw,     mm0, mm1);
                sts64(aBase + 2 * A_PL + sw, l0,  l1);
            }
            BAR_ARRIVE(1 + buf);             // tile full

#pragma unroll
            for (int i = 0; i < 8; i++) ar[i] = arn[i];
        }
#undef LOAD_A
    }
}

// ---------------------------------------------------------------------------
// Kernel 2: warp-per-row softmax + top-8 (redux argmax) + weights + aux.
// ---------------------------------------------------------------------------
__global__ void __launch_bounds__(RTHR)
router_kernel(float* __restrict__ out) {
    __shared__ float s_pr[RWARPS][NEXP];
    __shared__ int   s_cnt[NEXP];
    __shared__ int   s_last;
    const int tid  = threadIdx.x;
    const int lane = tid & 31;
    const int w    = tid >> 5;
    if (tid < NEXP) s_cnt[tid] = 0;
    __syncthreads();

    const int row = blockIdx.x * RWARPS + w;

    const float* p0p = &g_partial[0][(size_t)row * NEXP];
    const float* p1p = &g_partial[1][(size_t)row * NEXP];
    float l0 = p0p[lane] + p1p[lane];
    float l1 = p0p[lane + 32] + p1p[lane + 32];

    unsigned em = redux_max_u32(fenc(fmaxf(l0, l1)));
    float m = fdec(em);
    float p0 = __expf(l0 - m);
    float p1 = __expf(l1 - m);
    float sm = p0 + p1;
#pragma unroll
    for (int off = 16; off; off >>= 1)
        sm += __shfl_xor_sync(0xffffffffu, sm, off);
    float inv = 1.0f / sm;
    p0 *= inv;
    p1 *= inv;

    s_pr[w][lane]      = p0;
    s_pr[w][lane + 32] = p1;

    const int NEG1 = 0xBF800000;
    int b0i = __float_as_int(p0);
    int b1i = __float_as_int(p1);
    bool sel0 = false, sel1 = false;
    float wsum = 0.0f, myv = 0.0f;
    int myi = 0;
#pragma unroll
    for (int it = 0; it < TOPK; it++) {
        int c0 = sel0 ? NEG1 : b0i;
        int c1 = sel1 ? NEG1 : b1i;
        int mv = redux_max_s32(c0 > c1 ? c0 : c1);
        unsigned q0 = __ballot_sync(0xffffffffu, c0 == mv);
        unsigned q1 = __ballot_sync(0xffffffffu, c1 == mv);
        int idx = q0 ? (__ffs(q0) - 1) : (__ffs(q1) + 31);
        float fv = __int_as_float(mv);
        wsum += fv;
        if (idx == lane)           sel0 = true;
        else if (idx == lane + 32) sel1 = true;
        if (lane == it) { myv = fv; myi = idx; }
        if (lane == 0)  atomicAdd(&s_cnt[idx], 1);
    }

    float invw = 1.0f / fmaxf(wsum, 1e-8f);
    if (lane < TOPK) {
        out[(size_t)row * TOPK + lane] = (float)myi;
        out[(size_t)BATCH * TOPK + (size_t)row * TOPK + lane] = myv * invw;
    }

    __syncthreads();

    if (tid < NEXP) {
        float si = 0.0f;
#pragma unroll
        for (int ww = 0; ww < RWARPS; ww++) si += s_pr[ww][tid];
        g_bimp[blockIdx.x][tid] = si;
        g_bcnt[blockIdx.x][tid] = s_cnt[tid];
        __threadfence();
    }
    __syncthreads();
    if (tid == 0) {
        unsigned tk = atomicAdd(&g_done, 1u);
        s_last = (tk == gridDim.x - 1) ? 1 : 0;
    }
    __syncthreads();

    if (s_last) {
        __shared__ float s_ri[8][NEXP];
        __shared__ int   s_rc[8][NEXP];
        const int e  = tid & 63;
        const int ch = tid >> 6;
        float si = 0.0f;
        int   sc = 0;
#pragma unroll 8
        for (int b = ch * (RBLK / 8); b < (ch + 1) * (RBLK / 8); b++) {
            si += *(volatile float*)&g_bimp[b][e];
            sc += *(volatile int*)&g_bcnt[b][e];
        }
        s_ri[ch][e] = si;
        s_rc[ch][e] = sc;
        __syncthreads();
        if (tid < NEXP) {
            float ti = 0.0f;
            int   tc = 0;
#pragma unroll
            for (int c = 0; c < 8; c++) { ti += s_ri[c][tid]; tc += s_rc[c][tid]; }
            s_ri[0][tid] = (float)NEXP * (ti / (float)BATCH) *
                           ((float)tc / (float)(BATCH * TOPK));
        }
        __syncthreads();
        if (tid == 0) {
            float s = 0.0f;
#pragma unroll
            for (int i = 0; i < NEXP; i++) s += s_ri[0][i];
            out[(size_t)2 * BATCH * TOPK] = s;
        }
    }
}

// ---------------------------------------------------------------------------
extern "C" void kernel_launch(void* const* d_in, const int* in_sizes, int n_in,
                              void* d_out, int out_size) {
    const float* hs  = (const float*)d_in[0];
    const float* gw  = (const float*)d_in[1];
    float*       out = (float*)d_out;

    cudaFuncSetAttribute(gemm_tc, cudaFuncAttributeMaxDynamicSharedMemorySize,
                         SM_ALLOC);
    bsplit_kernel<<<256, 256>>>(gw);
    gemm_tc<<<dim3(BATCH / BM, KSPL), 256, SM_ALLOC>>>(hs);
    router_kernel<<<RBLK, RTHR>>>(out);
}

// round 14
// speedup vs baseline: 1.5702x; 1.5702x over previous
#include <cuda_runtime.h>
#include <cuda_bf16.h>
#include <cstdint>

// ---------------------------------------------------------------------------
// Problem constants
// ---------------------------------------------------------------------------
#define BATCH   8192
#define SEQ     8
#define HID     2048
#define NEXP    64
#define TOPK    8
#define ROWSTR  (SEQ * HID)

// GEMM config (byte-identical to the R11 51.7us kernel): BM=64, split-K=2,
// warps 0-3 consumers (m32n32, LDSM A + direct-LDG B frags + MMA),
// warps 4-7 producers (LDG A f32 -> split3 -> STS), 2-stage A pipeline.
#define BM      64
#define KT      64
#define KSPL    2
#define KHALF   (HID / KSPL)       // 1024
#define NT      (KHALF / KT)       // 16

#define A_PL    8192               // 64 rows x 128B
#define ABUF    (3 * A_PL)         // 24576
#define STAGE   ABUF
#define SM_ALLOC (2 * STAGE + 1024)   // 50176 -> 2 CTAs/SM

#define NCH     (HID / 16)         // 128 k16 chunks

// Router config: 256 blocks x 512 threads, 16 warps x 2 rows = 32 rows/block
#define RBLK    256
#define RTHR    512
#define RROWS   32

// Scratch (no allocation allowed)
__device__ float    g_partial[KSPL][BATCH * NEXP];  // 4 MB
__device__ uint32_t g_bfrag[3 * 8 * NCH * 64];      // 768 KB, frag-ordered B
__device__ float    g_bimp[RBLK][NEXP];
__device__ int      g_bcnt[RBLK][NEXP];
__device__ unsigned g_done;

// ---------------------------------------------------------------------------
// helpers
// ---------------------------------------------------------------------------
__device__ __forceinline__ uint32_t smem_to_u32(const void* p) {
    uint32_t a;
    asm("{ .reg .u64 t; cvta.to.shared.u64 t, %1; cvt.u32.u64 %0, t; }"
        : "=r"(a) : "l"(p));
    return a;
}
__device__ __forceinline__ void ldsm4(uint32_t* r, uint32_t addr) {
    asm volatile("ldmatrix.sync.aligned.m8n8.x4.shared.b16 {%0,%1,%2,%3}, [%4];"
                 : "=r"(r[0]), "=r"(r[1]), "=r"(r[2]), "=r"(r[3]) : "r"(addr));
}
__device__ __forceinline__ void mma16816(float* d, const uint32_t* a,
                                         const uint32_t* b) {
    asm volatile(
        "mma.sync.aligned.m16n8k16.row.col.f32.bf16.bf16.f32 "
        "{%0,%1,%2,%3}, {%4,%5,%6,%7}, {%8,%9}, {%0,%1,%2,%3};"
        : "+f"(d[0]), "+f"(d[1]), "+f"(d[2]), "+f"(d[3])
        : "r"(a[0]), "r"(a[1]), "r"(a[2]), "r"(a[3]), "r"(b[0]), "r"(b[1]));
}
__device__ __forceinline__ uint32_t pack_bf16(float lo, float hi) {
    uint32_t r;
    asm("cvt.rn.bf16x2.f32 %0, %1, %2;" : "=r"(r) : "f"(hi), "f"(lo));
    return r;
}
// fp32 -> 3x bf16 split (byte-identical to the R8/R11-passing kernels)
__device__ __forceinline__ void split3(float x, float y,
                                       uint32_t& h, uint32_t& m, uint32_t& l) {
    h = pack_bf16(x, y);
    float hx = __uint_as_float(h << 16);
    float hy = __uint_as_float(h & 0xffff0000u);
    float rx = x - hx, ry = y - hy;
    m = pack_bf16(rx, ry);
    float mx = __uint_as_float(m << 16);
    float my = __uint_as_float(m & 0xffff0000u);
    l = pack_bf16(rx - mx, ry - my);
}
__device__ __forceinline__ void sts64(uint32_t addr, uint32_t a, uint32_t b) {
    asm volatile("st.shared.v2.b32 [%0], {%1, %2};"
                 :: "r"(addr), "r"(a), "r"(b) : "memory");
}
#define BAR_SYNC(id)   asm volatile("bar.sync %0, 256;"   :: "r"(id) : "memory")
#define BAR_ARRIVE(id) asm volatile("bar.arrive %0, 256;" :: "r"(id) : "memory")

__device__ __forceinline__ int redux_max_s32(int v) {
    int r;
    asm("redux.sync.max.s32 %0, %1, 0xffffffff;" : "=r"(r) : "r"(v));
    return r;
}
__device__ __forceinline__ unsigned redux_max_u32(unsigned v) {
    unsigned r;
    asm("redux.sync.max.u32 %0, %1, 0xffffffff;" : "=r"(r) : "r"(v));
    return r;
}
__device__ __forceinline__ unsigned fenc(float f) {
    int b = __float_as_int(f);
    return (unsigned)(b ^ ((b >> 31) | 0x80000000));
}
__device__ __forceinline__ float fdec(unsigned u) {
    int b = (u & 0x80000000u) ? (int)(u ^ 0x80000000u) : (int)~u;
    return __int_as_float(b);
}

// ---------------------------------------------------------------------------
// Kernel 0: split gate_w into 3 bf16 planes in MMA FRAGMENT order.
// 4 independent float2 per thread (MLP=4). Byte layout identical to R11.
// ---------------------------------------------------------------------------
__global__ void __launch_bounds__(256)
bsplit_kernel(const float* __restrict__ gw) {
    const int tid0 = blockIdx.x * 256 + threadIdx.x;   // 0..16383
    if (tid0 == 0) g_done = 0u;

    float2 v[4];
#pragma unroll
    for (int j = 0; j < 4; j++) {
        int id = tid0 + j * 16384;
        int half = id & 1;
        int t    = (id >> 1) & 31;
        int c    = (id >> 6) & 127;
        int g    = id >> 13;
        int n  = g * 8 + (t >> 2);
        int k0 = c * 16 + (t & 3) * 2 + half * 8;
        v[j] = *(const float2*)(gw + (size_t)n * HID + k0);
    }
#pragma unroll
    for (int j = 0; j < 4; j++) {
        int id = tid0 + j * 16384;
        int half = id & 1;
        int t    = (id >> 1) & 31;
        int c    = (id >> 6) & 127;
        int g    = id >> 13;
        uint32_t h, m, l;
        split3(v[j].x, v[j].y, h, m, l);
        int fi = (g * NCH + c) * 64 + t * 2 + half;
        const int PL = 8 * NCH * 64;
        g_bfrag[fi]          = h;
        g_bfrag[PL + fi]     = m;
        g_bfrag[2 * PL + fi] = l;
    }
}

// ---------------------------------------------------------------------------
// Kernel 1: HMMA logits GEMM (R11, unchanged).
// ---------------------------------------------------------------------------
__global__ void __launch_bounds__(256, 2)
gemm_tc(const float* __restrict__ hs) {
    extern __shared__ char smem_raw[];
    const uint32_t sb = (smem_to_u32(smem_raw) + 1023u) & ~1023u;

    const int tid  = threadIdx.x;
    const int wid  = tid >> 5;
    const int lane = tid & 31;
    const int m0   = blockIdx.x * BM;
    const int sp   = blockIdx.y;
    const int k0   = sp * KHALF;

    if (wid < 4) {
        // =================== CONSUMER ===================
        const int wm = (wid & 1) * 32;
        const int wn = (wid >> 1) * 32;
        const int gbase = wn >> 3;

        uint32_t abase[2], amask[2];
#pragma unroll
        for (int mt = 0; mt < 2; mt++) {
            int row = wm + mt * 16 + (lane & 15);
            abase[mt] = (uint32_t)(row * 128 + (lane >> 4) * 16);
            amask[mt] = (uint32_t)((row & 7) << 4);
        }

        float acc[2][4][4];
#pragma unroll
        for (int a = 0; a < 2; a++)
#pragma unroll
            for (int b = 0; b < 4; b++)
#pragma unroll
                for (int c = 0; c < 4; c++) acc[a][b][c] = 0.0f;

        const int pa[6] = {0, 0, 1, 0, 2, 1};
        const int pb[6] = {0, 1, 0, 2, 0, 1};

        const int PL = 8 * NCH * 64;
        const int csp = sp * (KHALF / 16);

        uint2 bb0[3][4], bb1[3][4];
#define LOAD_B(dst, cc) do {                                                  \
    _Pragma("unroll")                                                         \
    for (int p = 0; p < 3; p++) {                                             \
        _Pragma("unroll")                                                     \
        for (int j = 0; j < 4; j++)                                           \
            (dst)[p][j] = __ldg((const uint2*)&g_bfrag[                       \
                p * PL + ((gbase + j) * NCH + (csp + (cc))) * 64] + lane);    \
    } } while (0)

        LOAD_B(bb0, 0);

        for (int t = 0; t < NT; t++) {
            const int buf = t & 1;
            const uint32_t aBase = sb + (uint32_t)buf * STAGE;

            BAR_SYNC(1 + buf);

#pragma unroll
            for (int kc = 0; kc < 4; kc++) {
                uint32_t af[3][2][4];
#pragma unroll
                for (int p = 0; p < 3; p++)
#pragma unroll
                    for (int mt = 0; mt < 2; mt++)
                        ldsm4(af[p][mt],
                              aBase + p * A_PL + ((abase[mt] + kc * 32) ^ amask[mt]));

                if (kc < 3) {
                    if (kc & 1) { LOAD_B(bb0, t * 4 + kc + 1); }
                    else        { LOAD_B(bb1, t * 4 + kc + 1); }
                } else if (t + 1 < NT) {
                    LOAD_B(bb0, t * 4 + 4);
                }

#pragma unroll
                for (int pr = 0; pr < 6; pr++) {
#pragma unroll
                    for (int mt = 0; mt < 2; mt++) {
#pragma unroll
                        for (int j = 0; j < 4; j++) {
                            const uint2* bf = (kc & 1) ? &bb1[pb[pr]][j]
                                                       : &bb0[pb[pr]][j];
                            mma16816(acc[mt][j], af[pa[pr]][mt],
                                     (const uint32_t*)bf);
                        }
                    }
                }
            }
            if (t + 2 < NT) BAR_ARRIVE(3 + buf);
        }
#undef LOAD_B

        const int gr = m0 + wm + (lane >> 2);
        const int gc = wn + (lane & 3) * 2;
#pragma unroll
        for (int mt = 0; mt < 2; mt++) {
#pragma unroll
            for (int j = 0; j < 4; j++) {
                int row = gr + mt * 16;
                int col = gc + j * 8;
                *(float2*)&g_partial[sp][(size_t)row * NEXP + col] =
                    make_float2(acc[mt][j][0], acc[mt][j][1]);
                *(float2*)&g_partial[sp][(size_t)(row + 8) * NEXP + col] =
                    make_float2(acc[mt][j][2], acc[mt][j][3]);
            }
        }
    } else {
        // =================== PRODUCER (A only) ===================
        const int wt = tid & 127;

        float4 ar[8], arn[8];
#define LOAD_A(t, dst) do {                                                   \
    int kk = k0 + (t) * KT;                                                   \
    _Pragma("unroll")                                                         \
    for (int i = 0; i < 8; i++) {                                             \
        int lin = wt + i * 128; int row = lin >> 4; int c4 = lin & 15;        \
        (dst)[i] = *(const float4*)(hs + (size_t)(m0 + row) * ROWSTR + kk + c4 * 4); \
    } } while (0)

        LOAD_A(0, ar);

        for (int t = 0; t < NT; t++) {
            const int buf = t & 1;
            const uint32_t aBase = sb + (uint32_t)buf * STAGE;

            if (t + 1 < NT) LOAD_A(t + 1, arn);
            if (t >= 2) BAR_SYNC(3 + buf);

#pragma unroll
            for (int i = 0; i < 8; i++) {
                int lin = wt + i * 128; int row = lin >> 4; int c4 = lin & 15;
                uint32_t off = (uint32_t)(row * 128 + c4 * 8);
                uint32_t sw  = off ^ ((off >> 3) & 0x70u);
                uint32_t h0, mm0, l0, h1, mm1, l1;
                split3(ar[i].x, ar[i].y, h0, mm0, l0);
                split3(ar[i].z, ar[i].w, h1, mm1, l1);
                sts64(aBase + sw,            h0,  h1);
                sts64(aBase + A_PL + sw,     mm0, mm1);
                sts64(aBase + 2 * A_PL + sw, l0,  l1);
            }
            BAR_ARRIVE(1 + buf);

#pragma unroll
            for (int i = 0; i < 8; i++) ar[i] = arn[i];
        }
#undef LOAD_A
    }
}

// ---------------------------------------------------------------------------
// Kernel 2: router, 2 rows per warp (interleaved redux chains for ILP).
// Per-row op sequence identical to R11 -> idx/weights bit-identical.
// ---------------------------------------------------------------------------
__global__ void __launch_bounds__(RTHR)
router_kernel(float* __restrict__ out) {
    __shared__ float s_pr[RROWS][NEXP];
    __shared__ int   s_cnt[NEXP];
    __shared__ int   s_last;
    const int tid  = threadIdx.x;
    const int lane = tid & 31;
    const int w    = tid >> 5;                 // 0..15
    if (tid < NEXP) s_cnt[tid] = 0;
    __syncthreads();

    const int row0 = blockIdx.x * RROWS + w * 2;

    // ---- load + sum split partials for both rows (independent chains) ----
    float l0[2], l1[2];
#pragma unroll
    for (int rr = 0; rr < 2; rr++) {
        const float* p0p = &g_partial[0][(size_t)(row0 + rr) * NEXP];
        const float* p1p = &g_partial[1][(size_t)(row0 + rr) * NEXP];
        l0[rr] = p0p[lane] + p1p[lane];
        l1[rr] = p0p[lane + 32] + p1p[lane + 32];
    }

    // ---- softmax (both rows interleaved) ----
    float p0[2], p1[2];
    {
        unsigned ea = redux_max_u32(fenc(fmaxf(l0[0], l1[0])));
        unsigned eb = redux_max_u32(fenc(fmaxf(l0[1], l1[1])));
        float ma = fdec(ea), mb = fdec(eb);
        p0[0] = __expf(l0[0] - ma); p1[0] = __expf(l1[0] - ma);
        p0[1] = __expf(l0[1] - mb); p1[1] = __expf(l1[1] - mb);
        float sa = p0[0] + p1[0], sb2 = p0[1] + p1[1];
#pragma unroll
        for (int off = 16; off; off >>= 1) {
            sa  += __shfl_xor_sync(0xffffffffu, sa, off);
            sb2 += __shfl_xor_sync(0xffffffffu, sb2, off);
        }
        float ia = 1.0f / sa, ib = 1.0f / sb2;
        p0[0] *= ia; p1[0] *= ia;
        p0[1] *= ib; p1[1] *= ib;
    }

    s_pr[w * 2 + 0][lane]      = p0[0];
    s_pr[w * 2 + 0][lane + 32] = p1[0];
    s_pr[w * 2 + 1][lane]      = p0[1];
    s_pr[w * 2 + 1][lane + 32] = p1[1];

    // ---- top-8 (two interleaved selection chains) ----
    const int NEG1 = 0xBF800000;
    int b0i[2] = { __float_as_int(p0[0]), __float_as_int(p0[1]) };
    int b1i[2] = { __float_as_int(p1[0]), __float_as_int(p1[1]) };
    bool sel0[2] = {false, false}, sel1[2] = {false, false};
    float wsum[2] = {0.0f, 0.0f}, myv[2] = {0.0f, 0.0f};
    int myi[2] = {0, 0};
#pragma unroll
    for (int it = 0; it < TOPK; it++) {
        int ca0 = sel0[0] ? NEG1 : b0i[0];
        int ca1 = sel1[0] ? NEG1 : b1i[0];
        int cb0 = sel0[1] ? NEG1 : b0i[1];
        int cb1 = sel1[1] ? NEG1 : b1i[1];
        int mva = redux_max_s32(ca0 > ca1 ? ca0 : ca1);
        int mvb = redux_max_s32(cb0 > cb1 ? cb0 : cb1);
        unsigned qa0 = __ballot_sync(0xffffffffu, ca0 == mva);
        unsigned qa1 = __ballot_sync(0xffffffffu, ca1 == mva);
        unsigned qb0 = __ballot_sync(0xffffffffu, cb0 == mvb);
        unsigned qb1 = __ballot_sync(0xffffffffu, cb1 == mvb);
        int ida = qa0 ? (__ffs(qa0) - 1) : (__ffs(qa1) + 31);
        int idb = qb0 ? (__ffs(qb0) - 1) : (__ffs(qb1) + 31);
        wsum[0] += __int_as_float(mva);
        wsum[1] += __int_as_float(mvb);
        if (ida == lane)           sel0[0] = true;
        else if (ida == lane + 32) sel1[0] = true;
        if (idb == lane)           sel0[1] = true;
        else if (idb == lane + 32) sel1[1] = true;
        if (lane == it) {
            myv[0] = __int_as_float(mva); myi[0] = ida;
            myv[1] = __int_as_float(mvb); myi[1] = idb;
        }
        if (lane == 0) {
            atomicAdd(&s_cnt[ida], 1);
            atomicAdd(&s_cnt[idb], 1);
        }
    }

#pragma unroll
    for (int rr = 0; rr < 2; rr++) {
        float invw = 1.0f / fmaxf(wsum[rr], 1e-8f);
        if (lane < TOPK) {
            const int grow = row0 + rr;
            out[(size_t)grow * TOPK + lane] = (float)myi[rr];
            out[(size_t)BATCH * TOPK + (size_t)grow * TOPK + lane] =
                myv[rr] * invw;
        }
    }

    __syncthreads();

    if (tid < NEXP) {
        float si = 0.0f;
#pragma unroll
        for (int ww = 0; ww < RROWS; ww++) si += s_pr[ww][tid];
        g_bimp[blockIdx.x][tid] = si;
        g_bcnt[blockIdx.x][tid] = s_cnt[tid];
        __threadfence();
    }
    __syncthreads();
    if (tid == 0) {
        unsigned tk = atomicAdd(&g_done, 1u);
        s_last = (tk == gridDim.x - 1) ? 1 : 0;
    }
    __syncthreads();

    if (s_last) {
        __shared__ float s_ri[8][NEXP];
        __shared__ int   s_rc[8][NEXP];
        const int e  = tid & 63;
        const int ch = tid >> 6;            // 0..7
        float si = 0.0f;
        int   sc = 0;
#pragma unroll 8
        for (int b = ch * (RBLK / 8); b < (ch + 1) * (RBLK / 8); b++) {
            si += *(volatile float*)&g_bimp[b][e];
            sc += *(volatile int*)&g_bcnt[b][e];
        }
        s_ri[ch][e] = si;
        s_rc[ch][e] = sc;
        __syncthreads();
        if (tid < NEXP) {
            float ti = 0.0f;
            int   tc = 0;
#pragma unroll
            for (int c = 0; c < 8; c++) { ti += s_ri[c][tid]; tc += s_rc[c][tid]; }
            s_ri[0][tid] = (float)NEXP * (ti / (float)BATCH) *
                           ((float)tc / (float)(BATCH * TOPK));
        }
        __syncthreads();
        if (tid == 0) {
            float s = 0.0f;
#pragma unroll
            for (int i = 0; i < NEXP; i++) s += s_ri[0][i];
            out[(size_t)2 * BATCH * TOPK] = s;
        }
    }
}

// ---------------------------------------------------------------------------
extern "C" void kernel_launch(void* const* d_in, const int* in_sizes, int n_in,
                              void* d_out, int out_size) {
    const float* hs  = (const float*)d_in[0];
    const float* gw  = (const float*)d_in[1];
    float*       out = (float*)d_out;

    cudaFuncSetAttribute(gemm_tc, cudaFuncAttributeMaxDynamicSharedMemorySize,
                         SM_ALLOC);
    bsplit_kernel<<<64, 256>>>(gw);
    gemm_tc<<<dim3(BATCH / BM, KSPL), 256, SM_ALLOC>>>(hs);
    router_kernel<<<RBLK, RTHR>>>(out);
}